// round 9
// baseline (speedup 1.0000x reference)
#include <cuda_runtime.h>
#include <cuda_fp16.h>

#define NPIXT 262144   // B*H*W = 4*256*256
#define HWSZ  65536    // H*W
#define NCH   32
#define NBLK  1024     // NPIXT / 256
#define TINYF 1.17549435e-38f
#define INFF  __int_as_float(0x7f800000)

// ---------------- scratch (__device__ globals: allocation-free, zero-init) -----------
__device__ __half2 g_pk[NPIXT * 32];   // per-pixel, per-channel (mw, den) fp16 pairs
__device__ int   g_tblV[8 * NPIXT];    // rank table, valid
__device__ int   g_tblH[8 * NPIXT];    // rank table, hard
__device__ unsigned char g_cls[NPIXT]; // s | valid<<3 | hard<<4
__device__ int   g_bcnt[16 * NBLK];    // per-block counts [(s*2+f)][block]
__device__ int   g_boff[16 * NBLK];    // exclusive prefix
__device__ int   g_count[8];
__device__ int   g_hcount[8];
__device__ float g_protoAcc[768];      // [k][s][c]; MUST be zero at kernel_launch entry
__device__ float g_posMW[8 * NCH];     // proto_mu_n * proto_w
__device__ float g_posDen[8 * NCH];    // proto_sigma * proto_w
__device__ float g_simL[8 * 7];        // sim/TEMP logits per (i,k)
__device__ float g_vnInv;

// ---------------- threefry2x32 (JAX-compatible, partitionable mode) ----------------
__device__ __forceinline__ void tf2x32(unsigned k0, unsigned k1,
                                       unsigned x0, unsigned x1,
                                       unsigned& o0, unsigned& o1) {
    unsigned ks2 = k0 ^ k1 ^ 0x1BD11BDAu;
    x0 += k0; x1 += k1;
#define TF_R(r) { x0 += x1; x1 = __funnelshift_l(x1, x1, (r)); x1 ^= x0; }
    TF_R(13) TF_R(15) TF_R(26) TF_R(6)   x0 += k1;  x1 += ks2 + 1u;
    TF_R(17) TF_R(29) TF_R(16) TF_R(24)  x0 += ks2; x1 += k0  + 2u;
    TF_R(13) TF_R(15) TF_R(26) TF_R(6)   x0 += k0;  x1 += k1  + 3u;
    TF_R(17) TF_R(29) TF_R(16) TF_R(24)  x0 += k1;  x1 += ks2 + 4u;
    TF_R(13) TF_R(15) TF_R(26) TF_R(6)   x0 += ks2; x1 += k0  + 5u;
#undef TF_R
    o0 = x0; o1 = x1;
}

__device__ __forceinline__ unsigned rbits(unsigned k0, unsigned k1, unsigned idx) {
    unsigned a, b;
    tf2x32(k0, k1, 0u, idx, a, b);
    return a ^ b;
}
__device__ __forceinline__ float u01(unsigned bits) {
    return __uint_as_float((bits >> 9) | 0x3F800000u) - 1.0f;
}

// ---------------- kernel 1: fused classify + transpose + prototype sums --------------
__global__ void __launch_bounds__(256) k_main(const float* __restrict__ w_in,
                                              const float* __restrict__ mu_in,
                                              const float* __restrict__ sg_in,
                                              const float* __restrict__ label,
                                              const float* __restrict__ mask,
                                              const float* __restrict__ prob) {
    __shared__ float tw[32][33], tm[32][33], ts[32][33];   // [channel][pixel]
    __shared__ float acc[8][768];          // [warp][k*256 + s*32 + c]
    __shared__ unsigned char codes[256];
    __shared__ int cnt[16];
    int t = threadIdx.x, warp = t >> 5, lane = t & 31;
    for (int j = t; j < 8 * 768; j += 256) ((float*)acc)[j] = 0.f;
    if (t < 16) cnt[t] = 0;

    int blockPix = blockIdx.x * 256;
    int n = blockPix + t;
    int b = n >> 16, x = n & 65535;

    // ---- classify ----
    float mk = mask[b * HWSZ + x];
    int s = 0;
#pragma unroll
    for (int k = 0; k < 8; k++) {
        float lv = label[(b * 8 + k) * HWSZ + x];
        if (lv > 0.5f) s = k;
    }
    bool valid = mk > 0.0f;
    float pv = prob[(b * 8 + s) * HWSZ + x];
    bool hard = valid && (pv < 0.97f);
    unsigned char code = (unsigned char)(s | (valid ? 8 : 0) | (hard ? 16 : 0));
    codes[t] = code;
    g_cls[n] = code;
    __syncthreads();   // covers acc/cnt zero + codes
    if (valid) {
        atomicAdd(&cnt[s * 2 + 0], 1);
        if (hard) atomicAdd(&cnt[s * 2 + 1], 1);
    }

    // ---- staged transpose (vectorized loads) ----
    size_t base = (size_t)b * (NCH * HWSZ) + (blockPix & 65535);
    int cg = lane >> 3;            // 0..3
    int g4 = (lane & 7) * 4;       // 0,4,...,28
    int cld = warp * 4 + cg;       // channel this thread loads
#pragma unroll 1
    for (int st = 0; st < 8; st++) {
        int pixOfs = st * 32;
        __syncthreads();
        {
            size_t a = base + (size_t)cld * HWSZ + pixOfs + g4;
            float4 vw = *(const float4*)(w_in + a);
            float4 vm = *(const float4*)(mu_in + a);
            float4 vs = *(const float4*)(sg_in + a);
            tw[cld][g4 + 0] = vw.x; tw[cld][g4 + 1] = vw.y; tw[cld][g4 + 2] = vw.z; tw[cld][g4 + 3] = vw.w;
            tm[cld][g4 + 0] = vm.x; tm[cld][g4 + 1] = vm.y; tm[cld][g4 + 2] = vm.z; tm[cld][g4 + 3] = vm.w;
            ts[cld][g4 + 0] = vs.x; ts[cld][g4 + 1] = vs.y; ts[cld][g4 + 2] = vs.z; ts[cld][g4 + 3] = vs.w;
        }
        __syncthreads();
#pragma unroll
        for (int j = 0; j < 4; j++) {
            int p = warp * 4 + j;
            int pin = pixOfs + p;            // pixel index within block
            int np = blockPix + pin;
            float wv = tw[lane][p];
            float mv = tm[lane][p];
            float sv = ts[lane][p];
            float nr2 = mv * mv;
#pragma unroll
            for (int ofs = 16; ofs; ofs >>= 1) nr2 += __shfl_xor_sync(0xffffffffu, nr2, ofs);
            float inv = 1.0f / fmaxf(sqrtf(nr2), 1e-12f);
            g_pk[(size_t)np * 32 + lane] = __floats2half2_rn((mv * inv) * wv, sv * wv);
            int pc = codes[pin];
            if (pc & 8) {
                int ps = pc & 7;
                float isw = __fdividef(wv, sv);
                acc[warp][0 * 256 + ps * 32 + lane] += isw;
                acc[warp][1 * 256 + ps * 32 + lane] += isw * mv;
                acc[warp][2 * 256 + ps * 32 + lane] += __frcp_rn(wv);
            }
        }
    }
    __syncthreads();
    if (t < 16) g_bcnt[t * NBLK + blockIdx.x] = cnt[t];
#pragma unroll
    for (int j = 0; j < 3; j++) {
        int idx = t + j * 256;
        float sum = 0.f;
#pragma unroll
        for (int w2 = 0; w2 < 8; w2++) sum += acc[w2][idx];
        if (sum != 0.f) atomicAdd(&g_protoAcc[idx], sum);
    }
}

// ---------------- kernel 2: warp-shfl prefix scan of block counts --------------------
__global__ void k_scan() {
    __shared__ int ws[32];
    int t = threadIdx.x, seq = blockIdx.x, warp = t >> 5, lane = t & 31;
    int v = g_bcnt[seq * NBLK + t];
    int x = v;
#pragma unroll
    for (int d = 1; d < 32; d <<= 1) {
        int y = __shfl_up_sync(0xffffffffu, x, d);
        if (lane >= d) x += y;
    }
    if (lane == 31) ws[warp] = x;
    __syncthreads();
    if (warp == 0) {
        int y = ws[lane];
#pragma unroll
        for (int d = 1; d < 32; d <<= 1) {
            int z = __shfl_up_sync(0xffffffffu, y, d);
            if (lane >= d) y += z;
        }
        ws[lane] = y;
    }
    __syncthreads();
    int incl = x + (warp ? ws[warp - 1] : 0);
    g_boff[seq * NBLK + t] = incl - v;
    if (t == NBLK - 1) {
        int s = seq >> 1;
        if ((seq & 1) == 0) g_count[s] = incl;
        else                g_hcount[s] = incl;
    }
}

// ---------------- kernel 3: scatter rank tables + (block 0) finalize -----------------
__global__ void k_scatter(float* out) {
    int n = blockIdx.x * 256 + threadIdx.x;
    int code = g_cls[n];
    int s = code & 7;
    bool valid = (code & 8) != 0, hard = (code & 16) != 0;
    __shared__ int wsum[8][8][2];  // [warp][class][flag]
    int warp = threadIdx.x >> 5, lane = threadIdx.x & 31;
    unsigned lmlt = (1u << lane) - 1u;
    int prefv = 0, prefh = 0;
#pragma unroll
    for (int k = 0; k < 8; k++) {
        unsigned mv = __ballot_sync(0xffffffffu, valid && (s == k));
        unsigned mh = __ballot_sync(0xffffffffu, hard && (s == k));
        if (s == k) { prefv = __popc(mv & lmlt); prefh = __popc(mh & lmlt); }
        if (lane == 0) { wsum[warp][k][0] = __popc(mv); wsum[warp][k][1] = __popc(mh); }
    }
    __syncthreads();
    int bofv = 0, bofh = 0;
    for (int w2 = 0; w2 < warp; w2++) { bofv += wsum[w2][s][0]; bofh += wsum[w2][s][1]; }
    if (valid) {
        int r = g_boff[(s * 2 + 0) * NBLK + blockIdx.x] + bofv + prefv;
        g_tblV[s * NPIXT + r] = n;
        if (hard) {
            int rh = g_boff[(s * 2 + 1) * NBLK + blockIdx.x] + bofh + prefh;
            g_tblH[s * NPIXT + rh] = n;
        }
    }

    // ---- finalize (block 0): prototypes, sim, valid_num; re-zero protoAcc ----
    if (blockIdx.x == 0) {
        int t = threadIdx.x;
        int ss = t >> 5, c = t & 31;
        float a0 = g_protoAcc[0 * 256 + t];
        float a1 = g_protoAcc[1 * 256 + t];
        float a2 = g_protoAcc[2 * 256 + t];
        g_protoAcc[0 * 256 + t] = 0.f;     // restore invariant for next replay
        g_protoAcc[1 * 256 + t] = 0.f;
        g_protoAcc[2 * 256 + t] = 0.f;
        float psig = 1.0f / a0;
        float pmu = a1 / a0;
        float pw = 1.0f / a2;
        float nr2 = pmu * pmu;
#pragma unroll
        for (int ofs = 16; ofs; ofs >>= 1) nr2 += __shfl_xor_sync(0xffffffffu, nr2, ofs);
        float inv = 1.0f / fmaxf(sqrtf(nr2), 1e-12f);
        float mun = pmu * inv;
        __shared__ float sMW[8][NCH], sDen[8][NCH];
        float mw = mun * pw, den = psig * pw;
        g_posMW[ss * NCH + c] = mw;
        g_posDen[ss * NCH + c] = den;
        sMW[ss][c] = mw;
        sDen[ss][c] = den;
        __syncthreads();
        if (t < 56) {
            int i = t / 7, k = t % 7, o = (i + 1 + k) & 7;
            float sum = 0.f;
            for (int cc = 0; cc < NCH; cc++) {
                float d = sMW[i][cc] - sMW[o][cc];
                float dn = sDen[i][cc] + sDen[o][cc];
                sum += d * d / dn + logf(dn);
            }
            g_simL[i * 7 + k] = (g_count[o] > 0) ? (-sum * (1.0f / 32.0f)) : -INFF;
        }
        if (t == 0) {
            int vn = 0;
            for (int s2 = 0; s2 < 8; s2++) vn += (g_count[s2] > 0) ? 1 : 0;
            g_vnInv = (vn > 0) ? 1.0f / (float)vn : 0.f;
            out[0] = 0.f;
        }
    }
}

// ---------------- MLS logits ---------------------------------------------------------
__device__ __forceinline__ float mls_logit_h(const float* __restrict__ aMW,
                                             const float* __restrict__ aDen,
                                             const __half2* __restrict__ bpk) {
    const uint4* u = (const uint4*)bpk;   // 8 uint4, each = 4 channels of (mw,den)
    float total = 0.f;
#pragma unroll
    for (int g = 0; g < 8; g++) {
        uint4 v = u[g];
        const __half2* h = (const __half2*)&v;
        float qs = 0.f, prod = 1.f;
#pragma unroll
        for (int i = 0; i < 4; i++) {
            float2 md = __half22float2(h[i]);   // x=mw, y=den
            int c = g * 4 + i;
            float den = aDen[c] + md.y;
            float d = aMW[c] - md.x;
            qs += __fdividef(d * d, den);
            prod *= den;
        }
        total += qs + __logf(prod);
    }
    return -total * (1.0f / 32.0f);  // _mls/TEMP
}

__device__ __forceinline__ float mls_logit_f(const float* __restrict__ aMW,
                                             const float* __restrict__ aDen,
                                             const float* __restrict__ bMW,
                                             const float* __restrict__ bDen) {
    float total = 0.f;
#pragma unroll
    for (int g = 0; g < 4; g++) {
        float qs = 0.f, prod = 1.f;
#pragma unroll
        for (int i = 0; i < 8; i++) {
            int c = g * 8 + i;
            float den = aDen[c] + bDen[c];
            float d = aMW[c] - bMW[c];
            qs += __fdividef(d * d, den);
            prod *= den;
        }
        total += qs + __logf(prod);
    }
    return -total * (1.0f / 32.0f);
}

// ---------------- kernel 4: fused sampling + logits + logsumexp + CE -----------------
__global__ void __launch_bounds__(256, 4) k_slog(float* out) {
    int i = blockIdx.x, q = blockIdx.y, t = threadIdx.x;
    int warp = t >> 5, lane = t & 31;
    __shared__ unsigned sk[4];           // k2a,k2b,k3a,k3b
    __shared__ int sap;
    __shared__ float ssim[7];
    __shared__ float aMW[NCH], aDen[NCH];
    __shared__ float sred[8];

    if (t < 7) ssim[t] = g_simL[i * 7 + t];
    // parallel prologue: three warps derive the three key chains
    if (t == 0) {
        unsigned ka, kb, k1a, k1b;
        tf2x32(0u, 42u, 0u, (unsigned)i, ka, kb);   // keys[i]
        tf2x32(ka, kb, 0u, 0u, k1a, k1b);           // k1
        float u = u01(rbits(k1a, k1b, (unsigned)q));
        int hc = g_hcount[i];
        int r = (int)(u * (float)hc);
        int cl = hc - 1; if (cl < 0) cl = 0;
        if (r > cl) r = cl;
        if (r < 0) r = 0;
        int ap = (hc > 0) ? g_tblH[i * NPIXT + r] : 0;
        if (ap < 0) ap = 0;
        if (ap >= NPIXT) ap = NPIXT - 1;
        sap = ap;
    } else if (t == 32) {
        unsigned ka, kb, a, b2;
        tf2x32(0u, 42u, 0u, (unsigned)i, ka, kb);
        tf2x32(ka, kb, 0u, 1u, a, b2);              // k2
        sk[0] = a; sk[1] = b2;
    } else if (t == 64) {
        unsigned ka, kb, a, b2;
        tf2x32(0u, 42u, 0u, (unsigned)i, ka, kb);
        tf2x32(ka, kb, 0u, 2u, a, b2);              // k3
        sk[2] = a; sk[3] = b2;
    }
    __syncthreads();
    if (t < NCH) {
        float2 md = __half22float2(g_pk[(size_t)sap * 32 + t]);
        aMW[t] = md.x;
        aDen[t] = md.y;
    }
    unsigned k2a = sk[0], k2b = sk[1], k3a = sk[2], k3b = sk[3];

    // ---- negative sampling (negative index = t) ----
    unsigned j = (unsigned)(q * 256 + t);
    unsigned b7 = j * 7u;
    float best = -INFF;
    int bi = 0;
#pragma unroll
    for (int k = 0; k < 7; k++) {
        float u = u01(rbits(k2a, k2b, b7 + k));
        u = fmaxf(u + TINYF, TINYF);
        float g = -__logf(-__logf(u));
        float v = g + ssim[k];
        if (v > best) { best = v; bi = k; }
    }
    int cls = (i + 1 + bi) & 7;
    int cnt = g_count[cls];
    float u3 = u01(rbits(k3a, k3b, j));
    int r = (int)(u3 * (float)cnt);
    int cl = cnt - 1; if (cl < 0) cl = 0;
    if (r > cl) r = cl;
    if (r < 0) r = 0;
    int p = g_tblV[cls * NPIXT + r];
    if (p < 0) p = 0;
    if (p >= NPIXT) p = NPIXT - 1;
    __syncthreads();   // anchor smem ready

    // ---- logits: lg0 = this thread's NEGATIVE, lg1 (t==0 only) = POSITIVE ----
    float lg0 = mls_logit_h(aMW, aDen, g_pk + (size_t)p * 32);
    float lg1 = (t == 0) ? mls_logit_f(aMW, aDen, g_posMW + i * NCH, g_posDen + i * NCH)
                         : -INFF;

    // ---- block logsumexp ----
    float mymax = fmaxf(lg0, lg1);
#pragma unroll
    for (int ofs = 16; ofs; ofs >>= 1) mymax = fmaxf(mymax, __shfl_xor_sync(0xffffffffu, mymax, ofs));
    if (lane == 0) sred[warp] = mymax;
    __syncthreads();
    if (t == 0) {
        float m = sred[0];
#pragma unroll
        for (int w2 = 1; w2 < 8; w2++) m = fmaxf(m, sred[w2]);
        sred[0] = m;
    }
    __syncthreads();
    float M = sred[0];
    __syncthreads();
    float ex = __expf(lg0 - M) + ((t == 0) ? __expf(lg1 - M) : 0.f);
#pragma unroll
    for (int ofs = 16; ofs; ofs >>= 1) ex += __shfl_xor_sync(0xffffffffu, ex, ofs);
    if (lane == 0) sred[warp] = ex;
    __syncthreads();
    if (t == 0) {
        float sum = 0.f;
#pragma unroll
        for (int w2 = 0; w2 < 8; w2++) sum += sred[w2];
        float lse = M + __logf(sum);
        bool ok = (g_hcount[i] > 0) && (g_count[i] > 0);
        if (ok) atomicAdd(out, (lse - lg1) * g_vnInv * (1.0f / 256.0f));
    }
}

// ---------------- launch ----------------
extern "C" void kernel_launch(void* const* d_in, const int* in_sizes, int n_in,
                              void* d_out, int out_size) {
    const float* weights = (const float*)d_in[0];
    const float* mu      = (const float*)d_in[1];
    const float* sigma   = (const float*)d_in[2];
    const float* label   = (const float*)d_in[3];
    const float* mask    = (const float*)d_in[4];
    const float* prob    = (const float*)d_in[5];
    float* out = (float*)d_out;

    k_main<<<NBLK, 256>>>(weights, mu, sigma, label, mask, prob);
    k_scan<<<16, NBLK>>>();
    k_scatter<<<NBLK, 256>>>(out);
    k_slog<<<dim3(8, 256), 256>>>(out);
}

// round 10
// speedup vs baseline: 1.0838x; 1.0838x over previous
#include <cuda_runtime.h>
#include <cuda_fp16.h>

#define NPIXT 262144   // B*H*W = 4*256*256
#define HWSZ  65536    // H*W
#define NCH   32
#define NBLK  1024     // NPIXT / 256
#define TINYF 1.17549435e-38f
#define INFF  __int_as_float(0x7f800000)

// ---------------- scratch (__device__ globals: allocation-free, zero-init) -----------
__device__ __half2 g_pk[NPIXT * 32];   // per-pixel, per-channel (mw, den) fp16 pairs
__device__ int   g_tblV[8 * NPIXT];    // rank table, valid
__device__ int   g_tblH[8 * NPIXT];    // rank table, hard
__device__ unsigned char g_cls[NPIXT]; // s | valid<<3 | hard<<4
__device__ int   g_bcnt[16 * NBLK];    // per-block counts [(s*2+f)][block]
__device__ int   g_boff[16 * NBLK];    // exclusive prefix
__device__ int   g_count[8];
__device__ int   g_hcount[8];
__device__ float g_protoAcc[768];      // [k][s][c]; MUST be zero at kernel_launch entry
__device__ float g_posMW[8 * NCH];     // proto_mu_n * proto_w
__device__ float g_posDen[8 * NCH];    // proto_sigma * proto_w
__device__ float g_simL[8 * 7];        // sim/TEMP logits per (i,k)
__device__ float g_vnInv;

// ---------------- threefry2x32 (JAX-compatible, partitionable mode) ----------------
__device__ __forceinline__ void tf2x32(unsigned k0, unsigned k1,
                                       unsigned x0, unsigned x1,
                                       unsigned& o0, unsigned& o1) {
    unsigned ks2 = k0 ^ k1 ^ 0x1BD11BDAu;
    x0 += k0; x1 += k1;
#define TF_R(r) { x0 += x1; x1 = __funnelshift_l(x1, x1, (r)); x1 ^= x0; }
    TF_R(13) TF_R(15) TF_R(26) TF_R(6)   x0 += k1;  x1 += ks2 + 1u;
    TF_R(17) TF_R(29) TF_R(16) TF_R(24)  x0 += ks2; x1 += k0  + 2u;
    TF_R(13) TF_R(15) TF_R(26) TF_R(6)   x0 += k0;  x1 += k1  + 3u;
    TF_R(17) TF_R(29) TF_R(16) TF_R(24)  x0 += k1;  x1 += ks2 + 4u;
    TF_R(13) TF_R(15) TF_R(26) TF_R(6)   x0 += ks2; x1 += k0  + 5u;
#undef TF_R
    o0 = x0; o1 = x1;
}

__device__ __forceinline__ unsigned rbits(unsigned k0, unsigned k1, unsigned idx) {
    unsigned a, b;
    tf2x32(k0, k1, 0u, idx, a, b);
    return a ^ b;
}
__device__ __forceinline__ float u01(unsigned bits) {
    return __uint_as_float((bits >> 9) | 0x3F800000u) - 1.0f;
}

// ---------------- kernel 1: fused classify + transpose + prototype sums --------------
__global__ void __launch_bounds__(256) k_main(const float* __restrict__ w_in,
                                              const float* __restrict__ mu_in,
                                              const float* __restrict__ sg_in,
                                              const float* __restrict__ label,
                                              const float* __restrict__ mask,
                                              const float* __restrict__ prob) {
    __shared__ float tw[32][33], tm[32][33], ts[32][33];   // [pixel][channel]
    __shared__ float acc[8][768];          // [warp][k*256 + s*32 + c]
    __shared__ unsigned char codes[256];
    __shared__ int cnt[16];
    int t = threadIdx.x, warp = t >> 5, lane = t & 31;
    for (int j = t; j < 8 * 768; j += 256) ((float*)acc)[j] = 0.f;
    if (t < 16) cnt[t] = 0;

    int blockPix = blockIdx.x * 256;
    int n = blockPix + t;
    int b = n >> 16, x = n & 65535;

    // ---- classify ----
    float mk = mask[b * HWSZ + x];
    int s = 0;
#pragma unroll
    for (int k = 0; k < 8; k++) {
        float lv = label[(b * 8 + k) * HWSZ + x];
        if (lv > 0.5f) s = k;
    }
    bool valid = mk > 0.0f;
    float pv = prob[(b * 8 + s) * HWSZ + x];
    bool hard = valid && (pv < 0.97f);
    unsigned char code = (unsigned char)(s | (valid ? 8 : 0) | (hard ? 16 : 0));
    codes[t] = code;
    g_cls[n] = code;
    __syncthreads();   // covers acc/cnt zero + codes
    if (valid) {
        atomicAdd(&cnt[s * 2 + 0], 1);
        if (hard) atomicAdd(&cnt[s * 2 + 1], 1);
    }

    // ---- staged transpose ----
    size_t base = (size_t)b * (NCH * HWSZ) + (blockPix & 65535);
#pragma unroll 1
    for (int st = 0; st < 8; st++) {
        int pixOfs = st * 32;
        __syncthreads();
#pragma unroll
        for (int i = 0; i < 4; i++) {
            int c = warp + i * 8;
            size_t a = base + (size_t)c * HWSZ + pixOfs + lane;
            tw[lane][c] = w_in[a];
            tm[lane][c] = mu_in[a];
            ts[lane][c] = sg_in[a];
        }
        __syncthreads();
#pragma unroll
        for (int j = 0; j < 4; j++) {
            int p = warp * 4 + j;
            int pin = pixOfs + p;            // pixel index within block
            int np = blockPix + pin;
            float wv = tw[p][lane];
            float mv = tm[p][lane];
            float sv = ts[p][lane];
            float nr2 = mv * mv;
#pragma unroll
            for (int ofs = 16; ofs; ofs >>= 1) nr2 += __shfl_xor_sync(0xffffffffu, nr2, ofs);
            float inv = 1.0f / fmaxf(sqrtf(nr2), 1e-12f);
            g_pk[(size_t)np * 32 + lane] = __floats2half2_rn((mv * inv) * wv, sv * wv);
            int pc = codes[pin];
            if (pc & 8) {
                int ps = pc & 7;
                float isw = __fdividef(wv, sv);
                acc[warp][0 * 256 + ps * 32 + lane] += isw;
                acc[warp][1 * 256 + ps * 32 + lane] += isw * mv;
                acc[warp][2 * 256 + ps * 32 + lane] += __frcp_rn(wv);
            }
        }
    }
    __syncthreads();
    if (t < 16) g_bcnt[t * NBLK + blockIdx.x] = cnt[t];
#pragma unroll
    for (int j = 0; j < 3; j++) {
        int idx = t + j * 256;
        float sum = 0.f;
#pragma unroll
        for (int w2 = 0; w2 < 8; w2++) sum += acc[w2][idx];
        if (sum != 0.f) atomicAdd(&g_protoAcc[idx], sum);
    }
}

// ---------------- kernel 2: warp-shfl prefix scan of block counts --------------------
__global__ void k_scan() {
    __shared__ int ws[32];
    int t = threadIdx.x, seq = blockIdx.x, warp = t >> 5, lane = t & 31;
    int v = g_bcnt[seq * NBLK + t];
    int x = v;
#pragma unroll
    for (int d = 1; d < 32; d <<= 1) {
        int y = __shfl_up_sync(0xffffffffu, x, d);
        if (lane >= d) x += y;
    }
    if (lane == 31) ws[warp] = x;
    __syncthreads();
    if (warp == 0) {
        int y = ws[lane];
#pragma unroll
        for (int d = 1; d < 32; d <<= 1) {
            int z = __shfl_up_sync(0xffffffffu, y, d);
            if (lane >= d) y += z;
        }
        ws[lane] = y;
    }
    __syncthreads();
    int incl = x + (warp ? ws[warp - 1] : 0);
    g_boff[seq * NBLK + t] = incl - v;
    if (t == NBLK - 1) {
        int s = seq >> 1;
        if ((seq & 1) == 0) g_count[s] = incl;
        else                g_hcount[s] = incl;
    }
}

// ---------------- kernel 3: scatter rank tables + (block 0) finalize -----------------
__global__ void k_scatter(float* out) {
    int n = blockIdx.x * 256 + threadIdx.x;
    int code = g_cls[n];
    int s = code & 7;
    bool valid = (code & 8) != 0, hard = (code & 16) != 0;
    __shared__ int wsum[8][8][2];  // [warp][class][flag]
    int warp = threadIdx.x >> 5, lane = threadIdx.x & 31;
    unsigned lmlt = (1u << lane) - 1u;
    int prefv = 0, prefh = 0;
#pragma unroll
    for (int k = 0; k < 8; k++) {
        unsigned mv = __ballot_sync(0xffffffffu, valid && (s == k));
        unsigned mh = __ballot_sync(0xffffffffu, hard && (s == k));
        if (s == k) { prefv = __popc(mv & lmlt); prefh = __popc(mh & lmlt); }
        if (lane == 0) { wsum[warp][k][0] = __popc(mv); wsum[warp][k][1] = __popc(mh); }
    }
    __syncthreads();
    int bofv = 0, bofh = 0;
    for (int w2 = 0; w2 < warp; w2++) { bofv += wsum[w2][s][0]; bofh += wsum[w2][s][1]; }
    if (valid) {
        int r = g_boff[(s * 2 + 0) * NBLK + blockIdx.x] + bofv + prefv;
        g_tblV[s * NPIXT + r] = n;
        if (hard) {
            int rh = g_boff[(s * 2 + 1) * NBLK + blockIdx.x] + bofh + prefh;
            g_tblH[s * NPIXT + rh] = n;
        }
    }

    // ---- finalize (block 0): prototypes, sim, valid_num; re-zero protoAcc ----
    if (blockIdx.x == 0) {
        int t = threadIdx.x;
        int ss = t >> 5, c = t & 31;
        float a0 = g_protoAcc[0 * 256 + t];
        float a1 = g_protoAcc[1 * 256 + t];
        float a2 = g_protoAcc[2 * 256 + t];
        g_protoAcc[0 * 256 + t] = 0.f;     // restore invariant for next replay
        g_protoAcc[1 * 256 + t] = 0.f;
        g_protoAcc[2 * 256 + t] = 0.f;
        float psig = 1.0f / a0;
        float pmu = a1 / a0;
        float pw = 1.0f / a2;
        float nr2 = pmu * pmu;
#pragma unroll
        for (int ofs = 16; ofs; ofs >>= 1) nr2 += __shfl_xor_sync(0xffffffffu, nr2, ofs);
        float inv = 1.0f / fmaxf(sqrtf(nr2), 1e-12f);
        float mun = pmu * inv;
        __shared__ float sMW[8][NCH], sDen[8][NCH];
        float mw = mun * pw, den = psig * pw;
        g_posMW[ss * NCH + c] = mw;
        g_posDen[ss * NCH + c] = den;
        sMW[ss][c] = mw;
        sDen[ss][c] = den;
        __syncthreads();
        if (t < 56) {
            int i = t / 7, k = t % 7, o = (i + 1 + k) & 7;
            float sum = 0.f;
            for (int cc = 0; cc < NCH; cc++) {
                float d = sMW[i][cc] - sMW[o][cc];
                float dn = sDen[i][cc] + sDen[o][cc];
                sum += d * d / dn + logf(dn);
            }
            g_simL[i * 7 + k] = (g_count[o] > 0) ? (-sum * (1.0f / 32.0f)) : -INFF;
        }
        if (t == 0) {
            int vn = 0;
            for (int s2 = 0; s2 < 8; s2++) vn += (g_count[s2] > 0) ? 1 : 0;
            g_vnInv = (vn > 0) ? 1.0f / (float)vn : 0.f;
            out[0] = 0.f;
        }
    }
}

// ---------------- MLS logits ---------------------------------------------------------
__device__ __forceinline__ float mls_logit_h(const float* __restrict__ aMW,
                                             const float* __restrict__ aDen,
                                             const __half2* __restrict__ bpk) {
    const uint4* u = (const uint4*)bpk;   // 8 uint4, each = 4 channels of (mw,den)
    float total = 0.f;
#pragma unroll
    for (int g = 0; g < 8; g++) {
        uint4 v = u[g];
        const __half2* h = (const __half2*)&v;
        float qs = 0.f, prod = 1.f;
#pragma unroll
        for (int i = 0; i < 4; i++) {
            float2 md = __half22float2(h[i]);   // x=mw, y=den
            int c = g * 4 + i;
            float den = aDen[c] + md.y;
            float d = aMW[c] - md.x;
            qs += __fdividef(d * d, den);
            prod *= den;
        }
        total += qs + __logf(prod);
    }
    return -total * (1.0f / 32.0f);  // _mls/TEMP
}

__device__ __forceinline__ float mls_logit_f(const float* __restrict__ aMW,
                                             const float* __restrict__ aDen,
                                             const float* __restrict__ bMW,
                                             const float* __restrict__ bDen) {
    float total = 0.f;
#pragma unroll
    for (int g = 0; g < 4; g++) {
        float qs = 0.f, prod = 1.f;
#pragma unroll
        for (int i = 0; i < 8; i++) {
            int c = g * 8 + i;
            float den = aDen[c] + bDen[c];
            float d = aMW[c] - bMW[c];
            qs += __fdividef(d * d, den);
            prod *= den;
        }
        total += qs + __logf(prod);
    }
    return -total * (1.0f / 32.0f);
}

// ---------------- kernel 4: fused sampling + logits + logsumexp + CE -----------------
__global__ void __launch_bounds__(256) k_slog(float* out) {
    int i = blockIdx.x, q = blockIdx.y, t = threadIdx.x;
    int warp = t >> 5, lane = t & 31;
    __shared__ unsigned sk[4];           // k2a,k2b,k3a,k3b
    __shared__ int sap;
    __shared__ float sexp[7];            // exp(-sim/TEMP) for exponential-race argmin
    __shared__ float aMW[NCH], aDen[NCH];
    __shared__ float sred[8];

    if (t < 7) sexp[t] = __expf(-g_simL[i * 7 + t]);
    // parallel prologue: three warps derive the three key chains
    if (t == 0) {
        unsigned ka, kb, k1a, k1b;
        tf2x32(0u, 42u, 0u, (unsigned)i, ka, kb);   // keys[i]
        tf2x32(ka, kb, 0u, 0u, k1a, k1b);           // k1
        float u = u01(rbits(k1a, k1b, (unsigned)q));
        int hc = g_hcount[i];
        int r = (int)(u * (float)hc);
        int cl = hc - 1; if (cl < 0) cl = 0;
        if (r > cl) r = cl;
        if (r < 0) r = 0;
        int ap = (hc > 0) ? g_tblH[i * NPIXT + r] : 0;
        if (ap < 0) ap = 0;
        if (ap >= NPIXT) ap = NPIXT - 1;
        sap = ap;
    } else if (t == 32) {
        unsigned ka, kb, a, b2;
        tf2x32(0u, 42u, 0u, (unsigned)i, ka, kb);
        tf2x32(ka, kb, 0u, 1u, a, b2);              // k2
        sk[0] = a; sk[1] = b2;
    } else if (t == 64) {
        unsigned ka, kb, a, b2;
        tf2x32(0u, 42u, 0u, (unsigned)i, ka, kb);
        tf2x32(ka, kb, 0u, 2u, a, b2);              // k3
        sk[2] = a; sk[3] = b2;
    }
    __syncthreads();
    if (t < NCH) {
        float2 md = __half22float2(g_pk[(size_t)sap * 32 + t]);
        aMW[t] = md.x;
        aDen[t] = md.y;
    }
    unsigned k2a = sk[0], k2b = sk[1], k3a = sk[2], k3b = sk[3];

    // ---- negative class sampling via exponential race (argmin (-ln u)*exp(-sim)) ----
    // Order-isomorphic to JAX's gumbel argmax: g_k + s_k = -ln w_k (strictly decreasing).
    unsigned j = (unsigned)(q * 256 + t);
    unsigned b7 = j * 7u;
    float wmin = INFF;
    int bi = 0;
#pragma unroll
    for (int k = 0; k < 7; k++) {
        float u = u01(rbits(k2a, k2b, b7 + k));
        u = fmaxf(u + TINYF, TINYF);
        float wv = -__logf(u) * sexp[k];
        if (wv < wmin) { wmin = wv; bi = k; }
    }
    int cls = (i + 1 + bi) & 7;
    int cnt = g_count[cls];
    float u3 = u01(rbits(k3a, k3b, j));
    int r = (int)(u3 * (float)cnt);
    int cl = cnt - 1; if (cl < 0) cl = 0;
    if (r > cl) r = cl;
    if (r < 0) r = 0;
    int p = g_tblV[cls * NPIXT + r];
    if (p < 0) p = 0;
    if (p >= NPIXT) p = NPIXT - 1;
    __syncthreads();   // anchor smem ready

    // ---- logits: lg0 = this thread's NEGATIVE, lg1 (t==0 only) = POSITIVE ----
    float lg0 = mls_logit_h(aMW, aDen, g_pk + (size_t)p * 32);
    float lg1 = (t == 0) ? mls_logit_f(aMW, aDen, g_posMW + i * NCH, g_posDen + i * NCH)
                         : 0.f;

    // ---- logsumexp with fixed shift M=0 (logits bounded: lg <= ~4) ----
    float ex = __expf(lg0) + ((t == 0) ? __expf(lg1) : 0.f);
#pragma unroll
    for (int ofs = 16; ofs; ofs >>= 1) ex += __shfl_xor_sync(0xffffffffu, ex, ofs);
    if (lane == 0) sred[warp] = ex;
    __syncthreads();
    if (t == 0) {
        float sum = 0.f;
#pragma unroll
        for (int w2 = 0; w2 < 8; w2++) sum += sred[w2];
        float lse = __logf(sum);
        bool ok = (g_hcount[i] > 0) && (g_count[i] > 0);
        if (ok) atomicAdd(out, (lse - lg1) * g_vnInv * (1.0f / 256.0f));
    }
}

// ---------------- launch ----------------
extern "C" void kernel_launch(void* const* d_in, const int* in_sizes, int n_in,
                              void* d_out, int out_size) {
    const float* weights = (const float*)d_in[0];
    const float* mu      = (const float*)d_in[1];
    const float* sigma   = (const float*)d_in[2];
    const float* label   = (const float*)d_in[3];
    const float* mask    = (const float*)d_in[4];
    const float* prob    = (const float*)d_in[5];
    float* out = (float*)d_out;

    k_main<<<NBLK, 256>>>(weights, mu, sigma, label, mask, prob);
    k_scan<<<16, NBLK>>>();
    k_scatter<<<NBLK, 256>>>(out);
    k_slog<<<dim3(8, 256), 256>>>(out);
}